// round 10
// baseline (speedup 1.0000x reference)
#include <cuda_runtime.h>
#include <cuda_fp16.h>
#include <math.h>
#include <stdint.h>

// ---------------- problem constants ----------------
#define NLVL   12
#define TBL    (1u << 19)
#define TMASK  (TBL - 1u)
#define EMBD   24
#define DOUT   257
#define TPB    256
#define TILE_P 256

#define PRIME_Y 2654435761u
#define PRIME_Z 805459861u

struct Params { int res[NLVL]; };

// ---------------- f32x2 packed helpers (sm_103a) ----------------
__device__ __forceinline__ unsigned long long pack2_f32(float lo, float hi) {
    unsigned long long r;
    asm("mov.b64 %0, {%1, %2};" : "=l"(r) : "r"(__float_as_uint(lo)), "r"(__float_as_uint(hi)));
    return r;
}
__device__ __forceinline__ unsigned long long fma_f32x2(unsigned long long a,
                                                        unsigned long long b,
                                                        unsigned long long c) {
    unsigned long long d;
    asm("fma.rn.f32x2 %0, %1, %2, %3;" : "=l"(d) : "l"(a), "l"(b), "l"(c));
    return d;
}
__device__ __forceinline__ float hsum_f32x2(unsigned long long v) {
    unsigned a, b;
    asm("mov.b64 {%0, %1}, %2;" : "=r"(a), "=r"(b) : "l"(v));
    return __uint_as_float(a) + __uint_as_float(b);
}
// half2 (as raw u32) -> packed f32x2 (ull)
__device__ __forceinline__ unsigned long long h2_to_f32x2(unsigned h2) {
    const __half2 h = *reinterpret_cast<const __half2*>(&h2);
    const float2 f = __half22float2(h);
    return pack2_f32(f.x, f.y);
}

__global__ __launch_bounds__(TPB, 2)
void hashsdf_kernel(const float* __restrict__ inputs,
                    const float* __restrict__ tables,
                    const float* __restrict__ W,
                    const float* __restrict__ bias,
                    float* __restrict__ out,
                    int N, Params prm)
{
    // fp16 feature-pair embedding tile: sEmbH[level][point] = half2{feat0, feat1}
    __shared__ __align__(16) __half2 sEmbH[NLVL][TILE_P];

    const int tid   = threadIdx.x;
    const int pbase = blockIdx.x * TILE_P;
    const int p     = pbase + tid;

    // ---------------- Phase 1: hash-grid encode (gather bound) ----------------
    float x = 0.f, y = 0.f, z = 0.f;
    if (p < N) {
        x = inputs[3 * p + 0];
        y = inputs[3 * p + 1];
        z = inputs[3 * p + 2];
    }

#pragma unroll
    for (int l = 0; l < NLVL; ++l) {
        const float rs = (float)prm.res[l];
        const float px = x * rs, py = y * rs, pz = z * rs;
        const float fx = floorf(px), fy = floorf(py), fz = floorf(pz);
        const float tx = px - fx, ty = py - fy, tz = pz - fz;

        const unsigned ix = (unsigned)fx, iy = (unsigned)fy, iz = (unsigned)fz;
        const unsigned hy0 = iy * PRIME_Y, hy1 = hy0 + PRIME_Y;
        const unsigned hz0 = iz * PRIME_Z, hz1 = hz0 + PRIME_Z;

        // x-pair trick: x-prime is 1 => x0/x1 corner indices are q and q^(ix^(ix+1)).
        // Even ix => XOR mask 1 => both corners live in one aligned float4.
        const unsigned xm   = ix ^ (ix + 1u);      // odd; ==1 iff ix even
        const bool     oddx = (ix & 1u) != 0u;

        const unsigned q00 = (ix ^ hy0 ^ hz0) & TMASK;
        const unsigned q01 = (ix ^ hy0 ^ hz1) & TMASK;
        const unsigned q10 = (ix ^ hy1 ^ hz0) & TMASK;
        const unsigned q11 = (ix ^ hy1 ^ hz1) & TMASK;

        const float4* __restrict__ t4 = (const float4*)tables + (size_t)l * (TBL / 2);
        const float2* __restrict__ t2 = (const float2*)tables + (size_t)l * TBL;

        // always load the float4 pair containing the x0 corner
        const float4 a00 = __ldg(t4 + (q00 >> 1));
        const float4 a01 = __ldg(t4 + (q01 >> 1));
        const float4 a10 = __ldg(t4 + (q10 >> 1));
        const float4 a11 = __ldg(t4 + (q11 >> 1));

        // x0 corner: half of a selected by parity of q
        const float f000x = (q00 & 1) ? a00.z : a00.x, f000y = (q00 & 1) ? a00.w : a00.y;
        const float f001x = (q01 & 1) ? a01.z : a01.x, f001y = (q01 & 1) ? a01.w : a01.y;
        const float f010x = (q10 & 1) ? a10.z : a10.x, f010y = (q10 & 1) ? a10.w : a10.y;
        const float f011x = (q11 & 1) ? a11.z : a11.x, f011y = (q11 & 1) ? a11.w : a11.y;

        // x1 corner: even ix -> other half of a; odd ix -> exact float2 gather
        float f100x, f100y, f101x, f101y, f110x, f110y, f111x, f111y;
        if (oddx) {
            const float2 d00 = __ldg(t2 + ((q00 ^ xm) & TMASK));
            const float2 d01 = __ldg(t2 + ((q01 ^ xm) & TMASK));
            const float2 d10 = __ldg(t2 + ((q10 ^ xm) & TMASK));
            const float2 d11 = __ldg(t2 + ((q11 ^ xm) & TMASK));
            f100x = d00.x; f100y = d00.y;
            f101x = d01.x; f101y = d01.y;
            f110x = d10.x; f110y = d10.y;
            f111x = d11.x; f111y = d11.y;
        } else {
            f100x = (q00 & 1) ? a00.x : a00.z;  f100y = (q00 & 1) ? a00.y : a00.w;
            f101x = (q01 & 1) ? a01.x : a01.z;  f101y = (q01 & 1) ? a01.y : a01.w;
            f110x = (q10 & 1) ? a10.x : a10.z;  f110y = (q10 & 1) ? a10.y : a10.w;
            f111x = (q11 & 1) ? a11.x : a11.z;  f111y = (q11 & 1) ? a11.y : a11.w;
        }

        const float ux = 1.f - tx, uy = 1.f - ty, uz = 1.f - tz;
        const float a0 = ux * uy, a1 = ux * ty, a2 = tx * uy, a3 = tx * ty;
        const float w000 = a0 * uz, w001 = a0 * tz;
        const float w010 = a1 * uz, w011 = a1 * tz;
        const float w100 = a2 * uz, w101 = a2 * tz;
        const float w110 = a3 * uz, w111 = a3 * tz;

        float e0, e1;
        e0 = w000 * f000x;           e1 = w000 * f000y;
        e0 = fmaf(w001, f001x, e0);  e1 = fmaf(w001, f001y, e1);
        e0 = fmaf(w010, f010x, e0);  e1 = fmaf(w010, f010y, e1);
        e0 = fmaf(w011, f011x, e0);  e1 = fmaf(w011, f011y, e1);
        e0 = fmaf(w100, f100x, e0);  e1 = fmaf(w100, f100y, e1);
        e0 = fmaf(w101, f101x, e0);  e1 = fmaf(w101, f101y, e1);
        e0 = fmaf(w110, f110x, e0);  e1 = fmaf(w110, f110y, e1);
        e0 = fmaf(w111, f111x, e0);  e1 = fmaf(w111, f111y, e1);

        sEmbH[l][tid] = __floats2half2_rn(e0, e1);   // STS.32 (fp16 staging)
    }

    __syncthreads();

    // ---------------- Phase 2: [24 x 257] linear head (FMA bound) ----------------
    // 4 column groups x 2 point-halves; thread owns cols c0=64g+lane, c1=c0+32.
    // One broadcast LDS.128 now delivers FOUR points' feature pairs (fp16),
    // halving phase-2 LDS wavefronts. Converts to f32x2 then fma.rn.f32x2.
    {
        const int wid  = tid >> 5;
        const int lane = tid & 31;
        const int g    = wid & 3;          // column group
        const int h    = wid >> 2;         // point half
        const int c0   = g * 64 + lane;
        const int c1   = c0 + 32;

        unsigned long long w0[NLVL], w1[NLVL];
#pragma unroll
        for (int l = 0; l < NLVL; ++l) {
            w0[l] = pack2_f32(__ldg(&W[(2 * l) * DOUT + c0]), __ldg(&W[(2 * l + 1) * DOUT + c0]));
            w1[l] = pack2_f32(__ldg(&W[(2 * l) * DOUT + c1]), __ldg(&W[(2 * l + 1) * DOUT + c1]));
        }
        const unsigned long long b0 = pack2_f32(__ldg(&bias[c0]), 0.f);
        const unsigned long long b1 = pack2_f32(__ldg(&bias[c1]), 0.f);

        const int pg_end = h * 128 + 128;
        for (int pg = h * 128; pg < pg_end; pg += 4) {
            unsigned long long acc0[4] = {b0, b0, b0, b0};
            unsigned long long acc1[4] = {b1, b1, b1, b1};
#pragma unroll
            for (int l = 0; l < NLVL; ++l) {
                const uint4 e4 = *(const uint4*)&sEmbH[l][pg];   // 4 points, broadcast
                const unsigned long long eA = h2_to_f32x2(e4.x);
                const unsigned long long eB = h2_to_f32x2(e4.y);
                const unsigned long long eC = h2_to_f32x2(e4.z);
                const unsigned long long eD = h2_to_f32x2(e4.w);
                acc0[0] = fma_f32x2(eA, w0[l], acc0[0]);
                acc1[0] = fma_f32x2(eA, w1[l], acc1[0]);
                acc0[1] = fma_f32x2(eB, w0[l], acc0[1]);
                acc1[1] = fma_f32x2(eB, w1[l], acc1[1]);
                acc0[2] = fma_f32x2(eC, w0[l], acc0[2]);
                acc1[2] = fma_f32x2(eC, w1[l], acc1[2]);
                acc0[3] = fma_f32x2(eD, w0[l], acc0[3]);
                acc1[3] = fma_f32x2(eD, w1[l], acc1[3]);
            }
#pragma unroll
            for (int i = 0; i < 4; ++i) {
                const size_t row = (size_t)(pbase + pg + i) * DOUT;
                __stcs(&out[row + c0], hsum_f32x2(acc0[i]));
                __stcs(&out[row + c1], hsum_f32x2(acc1[i]));
            }
        }
    }

    // ---------------- column 256 epilogue (DOUT odd) ----------------
    {
        float acc = __ldg(&bias[256]);
#pragma unroll
        for (int l = 0; l < NLVL; ++l) {
            const float2 e = __half22float2(sEmbH[l][tid]);
            acc = fmaf(e.x, __ldg(&W[(2 * l) * DOUT + 256]), acc);
            acc = fmaf(e.y, __ldg(&W[(2 * l + 1) * DOUT + 256]), acc);
        }
        if (p < N) __stcs(&out[(size_t)p * DOUT + 256], acc);
    }
}

extern "C" void kernel_launch(void* const* d_in, const int* in_sizes, int n_in,
                              void* d_out, int out_size) {
    const float* inputs = (const float*)d_in[0];
    const float* tables = (const float*)d_in[1];
    const float* W      = (const float*)d_in[2];
    const float* bias   = (const float*)d_in[3];
    float* out          = (float*)d_out;

    const int N = in_sizes[0] / 3;

    // Replicate numpy's RES computation bit-exactly (RES[11] is analytically 2048;
    // floor outcome depends on libm rounding — do NOT hardcode).
    Params prm;
    const double growth = exp((log(2048.0) - log(16.0)) / 11.0);
    for (int l = 0; l < NLVL; ++l)
        prm.res[l] = (int)floor(16.0 * pow(growth, (double)l));

    const int grid = (N + TILE_P - 1) / TILE_P;
    hashsdf_kernel<<<grid, TPB>>>(inputs, tables, W, bias, out, N, prm);
}

// round 11
// speedup vs baseline: 1.1288x; 1.1288x over previous
#include <cuda_runtime.h>
#include <math.h>
#include <stdint.h>

// ---------------- problem constants ----------------
#define NLVL   12
#define TBL    (1u << 19)
#define TMASK  (TBL - 1u)
#define EMBD   24
#define DOUT   257
#define TPB    256
#define TILE_P 256

#define PRIME_Y 2654435761u
#define PRIME_Z 805459861u

struct Params { int res[NLVL]; };

// ---------------- f32x2 packed helpers (sm_103a) ----------------
__device__ __forceinline__ unsigned long long pack2_f32(float lo, float hi) {
    unsigned long long r;
    asm("mov.b64 %0, {%1, %2};" : "=l"(r) : "r"(__float_as_uint(lo)), "r"(__float_as_uint(hi)));
    return r;
}
__device__ __forceinline__ unsigned long long fma_f32x2(unsigned long long a,
                                                        unsigned long long b,
                                                        unsigned long long c) {
    unsigned long long d;
    asm("fma.rn.f32x2 %0, %1, %2, %3;" : "=l"(d) : "l"(a), "l"(b), "l"(c));
    return d;
}
__device__ __forceinline__ float hsum_f32x2(unsigned long long v) {
    unsigned a, b;
    asm("mov.b64 {%0, %1}, %2;" : "=r"(a), "=r"(b) : "l"(v));
    return __uint_as_float(a) + __uint_as_float(b);
}
// named barrier over 128 threads (ids 1 and 2; warps never straddle halves)
__device__ __forceinline__ void half_bar(int id) {
    asm volatile("bar.sync %0, 128;" :: "r"(id) : "memory");
}

__global__ __launch_bounds__(TPB, 2)
void hashsdf_kernel(const float* __restrict__ inputs,
                    const float* __restrict__ tables,
                    const float* __restrict__ W,
                    const float* __restrict__ bias,
                    float* __restrict__ out,
                    int N, Params prm)
{
    // feature-pair-major embedding tile: sEmb2[level][point] = {feat0, feat1}
    __shared__ __align__(16) float2 sEmb2[NLVL][TILE_P];

    const int tid   = threadIdx.x;
    const int pbase = blockIdx.x * TILE_P;
    const int p     = pbase + tid;

    // ---------------- Phase 1: hash-grid encode (gather bound) ----------------
    float x = 0.f, y = 0.f, z = 0.f;
    if (p < N) {
        x = inputs[3 * p + 0];
        y = inputs[3 * p + 1];
        z = inputs[3 * p + 2];
    }

#pragma unroll
    for (int l = 0; l < NLVL; ++l) {
        const float rs = (float)prm.res[l];
        const float px = x * rs, py = y * rs, pz = z * rs;
        const float fx = floorf(px), fy = floorf(py), fz = floorf(pz);
        const float tx = px - fx, ty = py - fy, tz = pz - fz;

        const unsigned ix = (unsigned)fx, iy = (unsigned)fy, iz = (unsigned)fz;
        const unsigned hy0 = iy * PRIME_Y, hy1 = hy0 + PRIME_Y;
        const unsigned hz0 = iz * PRIME_Z, hz1 = hz0 + PRIME_Z;

        // x-pair trick: x-prime is 1 => x0/x1 corner indices are q and q^(ix^(ix+1)).
        // Even ix => XOR mask 1 => both corners live in one aligned float4.
        const unsigned xm   = ix ^ (ix + 1u);      // odd; ==1 iff ix even
        const bool     oddx = (ix & 1u) != 0u;

        const unsigned q00 = (ix ^ hy0 ^ hz0) & TMASK;
        const unsigned q01 = (ix ^ hy0 ^ hz1) & TMASK;
        const unsigned q10 = (ix ^ hy1 ^ hz0) & TMASK;
        const unsigned q11 = (ix ^ hy1 ^ hz1) & TMASK;

        const float4* __restrict__ t4 = (const float4*)tables + (size_t)l * (TBL / 2);
        const float2* __restrict__ t2 = (const float2*)tables + (size_t)l * TBL;

        // always load the float4 pair containing the x0 corner
        const float4 a00 = __ldg(t4 + (q00 >> 1));
        const float4 a01 = __ldg(t4 + (q01 >> 1));
        const float4 a10 = __ldg(t4 + (q10 >> 1));
        const float4 a11 = __ldg(t4 + (q11 >> 1));

        // x0 corner: half of a selected by parity of q
        const float f000x = (q00 & 1) ? a00.z : a00.x, f000y = (q00 & 1) ? a00.w : a00.y;
        const float f001x = (q01 & 1) ? a01.z : a01.x, f001y = (q01 & 1) ? a01.w : a01.y;
        const float f010x = (q10 & 1) ? a10.z : a10.x, f010y = (q10 & 1) ? a10.w : a10.y;
        const float f011x = (q11 & 1) ? a11.z : a11.x, f011y = (q11 & 1) ? a11.w : a11.y;

        // x1 corner: even ix -> other half of a; odd ix -> exact float2 gather
        float f100x, f100y, f101x, f101y, f110x, f110y, f111x, f111y;
        if (oddx) {
            const float2 d00 = __ldg(t2 + ((q00 ^ xm) & TMASK));
            const float2 d01 = __ldg(t2 + ((q01 ^ xm) & TMASK));
            const float2 d10 = __ldg(t2 + ((q10 ^ xm) & TMASK));
            const float2 d11 = __ldg(t2 + ((q11 ^ xm) & TMASK));
            f100x = d00.x; f100y = d00.y;
            f101x = d01.x; f101y = d01.y;
            f110x = d10.x; f110y = d10.y;
            f111x = d11.x; f111y = d11.y;
        } else {
            f100x = (q00 & 1) ? a00.x : a00.z;  f100y = (q00 & 1) ? a00.y : a00.w;
            f101x = (q01 & 1) ? a01.x : a01.z;  f101y = (q01 & 1) ? a01.y : a01.w;
            f110x = (q10 & 1) ? a10.x : a10.z;  f110y = (q10 & 1) ? a10.y : a10.w;
            f111x = (q11 & 1) ? a11.x : a11.z;  f111y = (q11 & 1) ? a11.y : a11.w;
        }

        const float ux = 1.f - tx, uy = 1.f - ty, uz = 1.f - tz;
        const float a0 = ux * uy, a1 = ux * ty, a2 = tx * uy, a3 = tx * ty;
        const float w000 = a0 * uz, w001 = a0 * tz;
        const float w010 = a1 * uz, w011 = a1 * tz;
        const float w100 = a2 * uz, w101 = a2 * tz;
        const float w110 = a3 * uz, w111 = a3 * tz;

        float e0, e1;
        e0 = w000 * f000x;           e1 = w000 * f000y;
        e0 = fmaf(w001, f001x, e0);  e1 = fmaf(w001, f001y, e1);
        e0 = fmaf(w010, f010x, e0);  e1 = fmaf(w010, f010y, e1);
        e0 = fmaf(w011, f011x, e0);  e1 = fmaf(w011, f011y, e1);
        e0 = fmaf(w100, f100x, e0);  e1 = fmaf(w100, f100y, e1);
        e0 = fmaf(w101, f101x, e0);  e1 = fmaf(w101, f101y, e1);
        e0 = fmaf(w110, f110x, e0);  e1 = fmaf(w110, f110y, e1);
        e0 = fmaf(w111, f111x, e0);  e1 = fmaf(w111, f111y, e1);

        sEmb2[l][tid] = make_float2(e0, e1);   // STS.64
    }

    // Half-block barrier: points 0-127 are produced AND consumed by warps 0-3;
    // points 128-255 by warps 4-7. The halves are independent, so sync only
    // within each half — the two 4-warp groups desynchronize and overlap
    // gather-phase with FMA-phase on the same SM.
    const int halfid = 1 + (tid >> 7);
    half_bar(halfid);

    // ---------------- Phase 2: [24 x 257] linear head (FMA bound) ----------------
    // 4 column groups x 2 point-halves; thread owns cols c0=64g+lane, c1=c0+32.
    // Feature pairs packed into fma.rn.f32x2 (accumulate even/odd k in lanes,
    // horizontal-add at the end). Stores stay warp-contiguous (1 wf each).
    {
        const int wid  = tid >> 5;
        const int lane = tid & 31;
        const int g    = wid & 3;          // column group
        const int h    = wid >> 2;         // point half (== tid>>7)
        const int c0   = g * 64 + lane;
        const int c1   = c0 + 32;

        unsigned long long w0[NLVL], w1[NLVL];
#pragma unroll
        for (int l = 0; l < NLVL; ++l) {
            w0[l] = pack2_f32(__ldg(&W[(2 * l) * DOUT + c0]), __ldg(&W[(2 * l + 1) * DOUT + c0]));
            w1[l] = pack2_f32(__ldg(&W[(2 * l) * DOUT + c1]), __ldg(&W[(2 * l + 1) * DOUT + c1]));
        }
        const unsigned long long b0 = pack2_f32(__ldg(&bias[c0]), 0.f);
        const unsigned long long b1 = pack2_f32(__ldg(&bias[c1]), 0.f);

        const int pg_end = h * 128 + 128;
        for (int pg = h * 128; pg < pg_end; pg += 4) {
            unsigned long long acc0[4] = {b0, b0, b0, b0};
            unsigned long long acc1[4] = {b1, b1, b1, b1};
#pragma unroll
            for (int l = 0; l < NLVL; ++l) {
                const ulonglong2 eA = *(const ulonglong2*)&sEmb2[l][pg];      // pts 0,1
                const ulonglong2 eB = *(const ulonglong2*)&sEmb2[l][pg + 2];  // pts 2,3
                acc0[0] = fma_f32x2(eA.x, w0[l], acc0[0]);
                acc1[0] = fma_f32x2(eA.x, w1[l], acc1[0]);
                acc0[1] = fma_f32x2(eA.y, w0[l], acc0[1]);
                acc1[1] = fma_f32x2(eA.y, w1[l], acc1[1]);
                acc0[2] = fma_f32x2(eB.x, w0[l], acc0[2]);
                acc1[2] = fma_f32x2(eB.x, w1[l], acc1[2]);
                acc0[3] = fma_f32x2(eB.y, w0[l], acc0[3]);
                acc1[3] = fma_f32x2(eB.y, w1[l], acc1[3]);
            }
#pragma unroll
            for (int i = 0; i < 4; ++i) {
                const size_t row = (size_t)(pbase + pg + i) * DOUT;
                __stcs(&out[row + c0], hsum_f32x2(acc0[i]));
                __stcs(&out[row + c1], hsum_f32x2(acc1[i]));
            }
        }
    }

    // ---------------- column 256 epilogue (DOUT odd) ----------------
    // thread tid reads point tid — within the same half-group, so the
    // half-barrier above already covers it.
    {
        float acc = __ldg(&bias[256]);
#pragma unroll
        for (int l = 0; l < NLVL; ++l) {
            const float2 e = sEmb2[l][tid];
            acc = fmaf(e.x, __ldg(&W[(2 * l) * DOUT + 256]), acc);
            acc = fmaf(e.y, __ldg(&W[(2 * l + 1) * DOUT + 256]), acc);
        }
        if (p < N) __stcs(&out[(size_t)p * DOUT + 256], acc);
    }
}

extern "C" void kernel_launch(void* const* d_in, const int* in_sizes, int n_in,
                              void* d_out, int out_size) {
    const float* inputs = (const float*)d_in[0];
    const float* tables = (const float*)d_in[1];
    const float* W      = (const float*)d_in[2];
    const float* bias   = (const float*)d_in[3];
    float* out          = (float*)d_out;

    const int N = in_sizes[0] / 3;

    // Replicate numpy's RES computation bit-exactly (RES[11] is analytically 2048;
    // floor outcome depends on libm rounding — do NOT hardcode).
    Params prm;
    const double growth = exp((log(2048.0) - log(16.0)) / 11.0);
    for (int l = 0; l < NLVL; ++l)
        prm.res[l] = (int)floor(16.0 * pow(growth, (double)l));

    const int grid = (N + TILE_P - 1) / TILE_P;
    hashsdf_kernel<<<grid, TPB>>>(inputs, tables, W, bias, out, N, prm);
}